// round 10
// baseline (speedup 1.0000x reference)
#include <cuda_runtime.h>
#include <cstdint>

// resRNN: x(256,1024,8), W1(521,512), b1(512), W2(512,1), b2(1)
// out = [output(256,1024,1) | implied_storage(256,1024,1)]
//
// 128 CTAs = 16 rowgroups x 8 colgroups; cluster(8) = one rowgroup.
// All cross-CTA exchange via DSMEM (peer smem) + per-source mbarriers.
// Warp w of CTA cg consumes source (cg+w)&7's exported tile. No global
// scratch, no per-step cluster barrier, no L2 polling.

#define TPB 256

// dynamic smem byte offsets
#define OFF_W     0           // 544*64*4 = 139264  W1 slice [k][64]
#define OFF_IT    139264      // 544*20*4 = 43520   inpT[k][20]
#define OFF_RED   182784      // 8*16*68*4 = 34816  k-partial spill
#define OFF_EXP   217600      // 2*1040*4 = 8320    export: [parity][64*16 tile + 16 partials]
#define OFF_B1    225920      // 64*4
#define OFF_W2    226176      // 64*4
#define OFF_S     226432      // 16*4
#define OFF_SPART 226496      // 8*16*4
#define OFF_BAR   227008      // 8 mbarriers * 8B
#define SMEM_BYTES 227072
#define EXP_STRIDE_B 4160     // 1040 floats

__device__ __forceinline__ float tanh_ex(float v) {
    float e = __expf(2.0f * v);
    return 1.0f - __fdividef(2.0f, e + 1.0f);
}
__device__ __forceinline__ uint32_t smem_u32(const void* p) {
    uint32_t a;
    asm("{ .reg .u64 t; cvta.to.shared.u64 t, %1; cvt.u32.u64 %0, t; }" : "=r"(a) : "l"(p));
    return a;
}
__device__ __forceinline__ uint32_t mapa_sh(uint32_t addr, uint32_t rank) {
    uint32_t r;
    asm("mapa.shared::cluster.u32 %0, %1, %2;" : "=r"(r) : "r"(addr), "r"(rank));
    return r;
}
__device__ __forceinline__ void bar_arrive_remote(uint32_t remaddr) {
    asm volatile("mbarrier.arrive.release.cluster.shared::cluster.b64 _, [%0];"
                 :: "r"(remaddr) : "memory");
}
__device__ __forceinline__ void bar_wait_parity(uint32_t addr, uint32_t parity) {
    uint32_t done;
    asm volatile(
        "{\n\t.reg .pred p;\n\t"
        "mbarrier.try_wait.parity.acquire.cluster.shared::cta.b64 p, [%1], %2, 0x989680;\n\t"
        "selp.b32 %0, 1, 0, p;\n\t}"
        : "=r"(done) : "r"(addr), "r"(parity) : "memory");
    while (!done) {
        asm volatile(
            "{\n\t.reg .pred p;\n\t"
            "mbarrier.try_wait.parity.acquire.cluster.shared::cta.b64 p, [%1], %2, 0x989680;\n\t"
            "selp.b32 %0, 1, 0, p;\n\t}"
            : "=r"(done) : "r"(addr), "r"(parity) : "memory");
    }
}
__device__ __forceinline__ float4 ld_rem4(uint32_t addr) {
    float4 v;
    asm volatile("ld.shared::cluster.v4.f32 {%0,%1,%2,%3}, [%4];"
                 : "=f"(v.x), "=f"(v.y), "=f"(v.z), "=f"(v.w) : "r"(addr) : "memory");
    return v;
}
__device__ __forceinline__ float ld_rem1(uint32_t addr) {
    float v;
    asm volatile("ld.shared::cluster.f32 %0, [%1];" : "=f"(v) : "r"(addr) : "memory");
    return v;
}

__global__ void __cluster_dims__(8, 1, 1) __launch_bounds__(256, 1)
resRNN_kernel(const float* __restrict__ x, const float* __restrict__ W1,
              const float* __restrict__ b1, const float* __restrict__ W2,
              const float* __restrict__ b2, float* __restrict__ dout)
{
    extern __shared__ char smraw[];
    float* Wsm   = (float*)(smraw + OFF_W);
    float* inpT  = (float*)(smraw + OFF_IT);
    float* red   = (float*)(smraw + OFF_RED);
    float* expT  = (float*)(smraw + OFF_EXP);
    float* b1s   = (float*)(smraw + OFF_B1);
    float* w2s   = (float*)(smraw + OFF_W2);
    float* s_sm  = (float*)(smraw + OFF_S);
    float* spart = (float*)(smraw + OFF_SPART);
    const uint32_t sb = smem_u32(smraw);

    const int tid  = threadIdx.x;
    const int warp = tid >> 5;
    const int lane = tid & 31;
    const int cg   = blockIdx.x;
    const int rg   = blockIdx.y;
    const int row0 = rg * 16;
    const int src  = (cg + warp) & 7;

    // ---- init ----
    for (int i = tid; i < 544 * 16; i += TPB) {
        int k = i >> 4, f4 = i & 15;
        float4 v = make_float4(0.f, 0.f, 0.f, 0.f);
        if (k < 521) v = *(const float4*)&W1[k * 512 + cg * 64 + f4 * 4];
        *(float4*)&Wsm[k * 64 + f4 * 4] = v;
    }
    for (int i = tid; i < 544 * 20; i += TPB) inpT[i] = 0.f;
    if (tid < 64) { b1s[tid] = b1[cg * 64 + tid]; w2s[tid] = W2[cg * 64 + tid]; }
    if (tid < 16) s_sm[tid] = 0.f;
    if (tid < 128) spart[tid] = 0.f;
    if (tid == 0) {
        #pragma unroll
        for (int j = 0; j < 8; ++j)
            asm volatile("mbarrier.init.shared.b64 [%0], 1;"
                         :: "r"(sb + OFF_BAR + j * 8) : "memory");
    }
    const float b2v = b2[0];
    float* outp = dout;
    float* stop = dout + 256 * 1024;

    // remote addresses: per-warp export buffers of src; tid0: peer bar slots
    const uint32_t remExp0 = mapa_sh(sb + OFF_EXP, src);
    const uint32_t remExp1 = mapa_sh(sb + OFF_EXP + EXP_STRIDE_B, src);
    uint32_t remBar[8];
    if (tid == 0) {
        #pragma unroll
        for (int p_ = 0; p_ < 8; ++p_)
            remBar[p_] = mapa_sh(sb + OFF_BAR + cg * 8, p_);
    }

    // xpre: lane<16 holds x_t[row=lane][comp=warp]
    float xpre = 0.f;
    if (lane < 16) xpre = x[(row0 + lane) * 8192 + warp];

    __syncthreads();
    asm volatile("barrier.cluster.arrive.aligned;" ::: "memory");
    asm volatile("barrier.cluster.wait.aligned;" ::: "memory");

    for (int t = 0; t < 1024; ++t) {
        const int pw = t & 1;

        // ---- Phase X: stage x_t row; wait + pull source tile (step t-1) ----
        if (lane < 16) inpT[warp * 20 + lane] = xpre;
        if (t < 1023 && lane < 16)
            xpre = x[(row0 + lane) * 8192 + (t + 1) * 8 + warp];

        if (t > 0 && src != cg) {
            bar_wait_parity(sb + OFF_BAR + src * 8, (uint32_t)((t - 1) & 1));
            const uint32_t rb = ((t - 1) & 1) ? remExp1 : remExp0;
            // tile is [col][row] col-major: lane pulls cols 2*lane, 2*lane+1
            uint32_t a = rb + (uint32_t)(2 * lane * 16) * 4;
            float4 q0 = ld_rem4(a +   0), q1 = ld_rem4(a +  16);
            float4 q2 = ld_rem4(a +  32), q3 = ld_rem4(a +  48);
            float4 q4 = ld_rem4(a +  64), q5 = ld_rem4(a +  80);
            float4 q6 = ld_rem4(a +  96), q7 = ld_rem4(a + 112);
            float* d0 = &inpT[(9 + 64 * src + 2 * lane) * 20];
            float* d1 = d0 + 20;
            ((float4*)d0)[0] = q0; ((float4*)d0)[1] = q1;
            ((float4*)d0)[2] = q2; ((float4*)d0)[3] = q3;
            ((float4*)d1)[0] = q4; ((float4*)d1)[1] = q5;
            ((float4*)d1)[2] = q6; ((float4*)d1)[3] = q7;
            if (lane < 16)
                spart[src * 16 + lane] = ld_rem1(rb + 1024 * 4 + lane * 4);
        }
        __syncwarp();

        // ---- GEMM: 64 source hx rows + 1 x row; cols (2*lane, 2*lane+1) ----
        unsigned long long acc0[8], acc1[8];
        #pragma unroll
        for (int i = 0; i < 8; ++i) { acc0[i] = 0ull; acc1[i] = 0ull; }
        {
            const float* Ip = inpT + (9 + 64 * src) * 20;
            const float* Wp = Wsm + (9 + 64 * src) * 64 + 2 * lane;
            #pragma unroll 4
            for (int kk = 0; kk < 64; ++kk) {
                unsigned long long pr_[8];
                #pragma unroll
                for (int j = 0; j < 4; ++j) {
                    ulonglong2 q = *(const ulonglong2*)(Ip + kk * 20 + 4 * j);
                    pr_[2 * j] = q.x; pr_[2 * j + 1] = q.y;
                }
                float2 wv = *(const float2*)(Wp + kk * 64);
                unsigned long long w00, w11;
                asm("mov.b64 %0, {%1, %1};" : "=l"(w00) : "f"(wv.x));
                asm("mov.b64 %0, {%1, %1};" : "=l"(w11) : "f"(wv.y));
                #pragma unroll
                for (int p = 0; p < 8; ++p) {
                    asm("fma.rn.f32x2 %0, %1, %2, %0;" : "+l"(acc0[p]) : "l"(pr_[p]), "l"(w00));
                    asm("fma.rn.f32x2 %0, %1, %2, %0;" : "+l"(acc1[p]) : "l"(pr_[p]), "l"(w11));
                }
            }
            const float* Ipx = inpT + warp * 20;
            unsigned long long pr_[8];
            #pragma unroll
            for (int j = 0; j < 4; ++j) {
                ulonglong2 q = *(const ulonglong2*)(Ipx + 4 * j);
                pr_[2 * j] = q.x; pr_[2 * j + 1] = q.y;
            }
            float2 wv = *(const float2*)(Wsm + warp * 64 + 2 * lane);
            unsigned long long w00, w11;
            asm("mov.b64 %0, {%1, %1};" : "=l"(w00) : "f"(wv.x));
            asm("mov.b64 %0, {%1, %1};" : "=l"(w11) : "f"(wv.y));
            #pragma unroll
            for (int p = 0; p < 8; ++p) {
                asm("fma.rn.f32x2 %0, %1, %2, %0;" : "+l"(acc0[p]) : "l"(pr_[p]), "l"(w00));
                asm("fma.rn.f32x2 %0, %1, %2, %0;" : "+l"(acc1[p]) : "l"(pr_[p]), "l"(w11));
            }
        }

        // ---- spill k-partials ----
        #pragma unroll
        for (int p = 0; p < 8; ++p) {
            float2 a0 = *(float2*)&acc0[p];
            float2 a1 = *(float2*)&acc1[p];
            *(float2*)&red[(warp * 16 + 2 * p)     * 68 + 2 * lane] = make_float2(a0.x, a1.x);
            *(float2*)&red[(warp * 16 + 2 * p + 1) * 68 + 2 * lane] = make_float2(a0.y, a1.y);
        }
        __syncthreads();

        // ---- reduce + mass balance + tanh + export ----
        {
            int r = tid >> 4, c4 = (tid & 15) * 4;
            float4 v = make_float4(0.f, 0.f, 0.f, 0.f);
            #pragma unroll
            for (int w = 0; w < 8; ++w) {
                float4 p = *(const float4*)&red[(w * 16 + r) * 68 + c4];
                v.x += p.x; v.y += p.y; v.z += p.z; v.w += p.w;
            }
            float o = 0.f;
            if (t > 0) {
                o = b2v;
                #pragma unroll
                for (int j = 0; j < 8; ++j) o += spart[j * 16 + r];
            }
            float s = s_sm[r] + inpT[r] - o;        // inpT[r] = x_t[0][row r]
            float4 w8 = *(const float4*)&Wsm[8 * 64 + c4];
            v.x += s * w8.x; v.y += s * w8.y; v.z += s * w8.z; v.w += s * w8.w;

            v.x = tanh_ex(v.x + b1s[c4 + 0]);
            v.y = tanh_ex(v.y + b1s[c4 + 1]);
            v.z = tanh_ex(v.z + b1s[c4 + 2]);
            v.w = tanh_ex(v.w + b1s[c4 + 3]);

            // own tile straight into own inpT (read next step by warp 0)
            inpT[(9 + 64 * cg + c4 + 0) * 20 + r] = v.x;
            inpT[(9 + 64 * cg + c4 + 1) * 20 + r] = v.y;
            inpT[(9 + 64 * cg + c4 + 2) * 20 + r] = v.z;
            inpT[(9 + 64 * cg + c4 + 3) * 20 + r] = v.w;
            // export tile (col-major [col][row]) for peers
            float* eb = expT + pw * 1040;
            eb[(c4 + 0) * 16 + r] = v.x;
            eb[(c4 + 1) * 16 + r] = v.y;
            eb[(c4 + 2) * 16 + r] = v.z;
            eb[(c4 + 3) * 16 + r] = v.w;
            // readout partial
            float p = v.x * w2s[c4] + v.y * w2s[c4 + 1] + v.z * w2s[c4 + 2] + v.w * w2s[c4 + 3];
            #pragma unroll
            for (int off = 8; off > 0; off >>= 1)
                p += __shfl_xor_sync(0xffffffffu, p, off);
            if ((tid & 15) == 0) {
                s_sm[r] = s;                         // safe: all row-r reads precede (shfl synced warp)
                spart[cg * 16 + r] = p;              // self partial, local
                eb[1024 + r] = p;                    // exported partial
                if (cg == 0) {
                    if (t > 0) outp[(row0 + r) * 1024 + (t - 1)] = o;
                    stop[(row0 + r) * 1024 + t] = s;
                }
            }
        }
        __syncthreads();
        // ---- publish: arrive on each peer's bar[cg] ----
        if (tid == 0) {
            #pragma unroll
            for (int p_ = 0; p_ < 8; ++p_)
                if (p_ != cg) bar_arrive_remote(remBar[p_]);
        }
    }

    // ---- epilogue: out_{1023} ----
    if (src != cg) {
        bar_wait_parity(sb + OFF_BAR + src * 8, 1u);   // publishes of step 1023
        if (lane < 16)
            spart[src * 16 + lane] = ld_rem1(remExp1 + 1024 * 4 + lane * 4);
    }
    __syncthreads();
    if (cg == 0 && tid < 16) {
        float o = b2v;
        #pragma unroll
        for (int g = 0; g < 8; ++g) o += spart[g * 16 + tid];
        outp[(row0 + tid) * 1024 + 1023] = o;
    }
    // keep smem alive until all peers finished their last remote reads
    asm volatile("barrier.cluster.arrive.aligned;" ::: "memory");
    asm volatile("barrier.cluster.wait.aligned;" ::: "memory");
}

extern "C" void kernel_launch(void* const* d_in, const int* in_sizes, int n_in,
                              void* d_out, int out_size) {
    const float* x  = (const float*)d_in[0];
    const float* W1 = (const float*)d_in[1];
    const float* b1 = (const float*)d_in[2];
    const float* W2 = (const float*)d_in[3];
    const float* b2 = (const float*)d_in[4];
    float* out = (float*)d_out;

    cudaFuncSetAttribute(resRNN_kernel, cudaFuncAttributeMaxDynamicSharedMemorySize, SMEM_BYTES);

    dim3 grid(8, 16, 1);   // cluster (8,1,1) = one rowgroup
    dim3 block(TPB, 1, 1);
    resRNN_kernel<<<grid, block, SMEM_BYTES>>>(x, W1, b1, W2, b2, out);
}

// round 14
// speedup vs baseline: 1.5025x; 1.5025x over previous
#include <cuda_runtime.h>
#include <cstdint>

// resRNN: x(256,1024,8), W1(521,512), b1(512), W2(512,1), b2(1)
// out = [output(256,1024,1) | implied_storage(256,1024,1)]
//
// R6 kernel (proven replay-stable) with tanh_ex replacing tanhf.
// 128 CTAs = 16 rowgroups x 8 colgroups. Cluster(8) = one rowgroup.
// Each CTA: 16 batch rows x 64 hidden cols, W1 slice resident in smem.
// 8 warps = 8 k-parts (68 k each); lane = col-pair; fma.rn.f32x2 accumulators.

#define TPB 256

static __device__ float g_hx[2][256][512];       // double-buffered hidden state
static __device__ float g_part[2][16][8][16];    // per-(rg,cg,row) readout partials

// shared memory layout (float offsets); inpT stride = 20 (16 rows + 4 pad, 16B-aligned quads)
#define OFF_W    0              // 544*64   = 34816 floats
#define OFF_IT   34816          // 544*20   = 10880 floats (inpT[k][20])
#define OFF_RED  45696          // 8*16*68  =  8704 floats
#define OFF_B1   54400          // 64
#define OFF_W2   54464          // 64
#define OFF_S    54528          // 16
#define SMEM_FLOATS 54544
#define SMEM_BYTES (SMEM_FLOATS * 4)

__device__ __forceinline__ float tanh_ex(float v) {
    // 1 - 2/(e^{2v}+1); saturates correctly for large |v|. Validated at 1.2e-6.
    float e = __expf(2.0f * v);
    return 1.0f - __fdividef(2.0f, e + 1.0f);
}

__global__ void __cluster_dims__(8, 1, 1) __launch_bounds__(256, 1)
resRNN_kernel(const float* __restrict__ x, const float* __restrict__ W1,
              const float* __restrict__ b1, const float* __restrict__ W2,
              const float* __restrict__ b2, float* __restrict__ dout)
{
    extern __shared__ float sm[];
    float* Wsm  = sm + OFF_W;
    float* inpT = sm + OFF_IT;
    float* red  = sm + OFF_RED;
    float* b1s  = sm + OFF_B1;
    float* w2s  = sm + OFF_W2;
    float* s_sm = sm + OFF_S;

    const int tid  = threadIdx.x;
    const int warp = tid >> 5;     // k-partition 0..7
    const int lane = tid & 31;
    const int cg   = blockIdx.x;   // colgroup 0..7
    const int rg   = blockIdx.y;   // rowgroup 0..15
    const int row0 = rg * 16;

    // ---- init: load W1 slice [544 x 64] (zero-pad k>=521), zero inpT ----
    for (int i = tid; i < 544 * 16; i += TPB) {
        int k = i >> 4, f4 = i & 15;
        float4 v = make_float4(0.f, 0.f, 0.f, 0.f);
        if (k < 521) v = *(const float4*)&W1[k * 512 + cg * 64 + f4 * 4];
        *(float4*)&Wsm[k * 64 + f4 * 4] = v;
    }
    for (int i = tid; i < 544 * 20; i += TPB) inpT[i] = 0.f;
    if (tid < 64) { b1s[tid] = b1[cg * 64 + tid]; w2s[tid] = W2[cg * 64 + tid]; }
    const float b2v = b2[0];
    float* outp = dout;
    float* stop = dout + 256 * 1024;

    // pre-loop: stage x_0 into inpT, s_0 = x_0[0]; prefetch x_1
    const int xr = tid >> 3, xc = tid & 7;
    float xpre = 0.f, x0pre = 0.f;
    if (tid < 128) {
        float xv = x[(row0 + xr) * 8192 + xc];
        inpT[xc * 20 + xr] = xv;
        xpre = x[(row0 + xr) * 8192 + 8 + xc];         // x_1
    }
    if (tid < 16) {
        float s = x[(row0 + tid) * 8192];              // s_0 = x_0[0] (prev out = 0)
        s_sm[tid] = s;
        inpT[8 * 20 + tid] = s;
        if (cg == 0) stop[(row0 + tid) * 1024] = s;
        x0pre = x[(row0 + tid) * 8192 + 8];            // x_1[0] (for Phase A at t=1)
    }
    __syncthreads();

    for (int t = 0; t < 1024; ++t) {
        const int pw = t & 1;        // write parity
        const int pr = pw ^ 1;       // read parity = (t-1)&1

        // ---- Phase A: gather out_{t-1}; mass balance; transpose hx into inpT ----
        if (t > 0) {
            if (tid < 16) {
                float o = b2v;
                #pragma unroll
                for (int g = 0; g < 8; ++g) o += __ldcg(&g_part[pr][rg][g][tid]);
                // s_t = s_{t-1} + x_t[0] - out_{t-1}
                float s = s_sm[tid] + x0pre - o;
                s_sm[tid] = s;
                inpT[8 * 20 + tid] = s;
                if (cg == 0) {
                    outp[(row0 + tid) * 1024 + (t - 1)] = o;
                    stop[(row0 + tid) * 1024 + t] = s;
                }
            }
            // hx transpose: thread owns hidden cols tid and tid+256
            float v0[16], v1[16];
            #pragma unroll
            for (int r = 0; r < 16; ++r) v0[r] = __ldcg(&g_hx[pr][row0 + r][tid]);
            #pragma unroll
            for (int r = 0; r < 16; ++r) v1[r] = __ldcg(&g_hx[pr][row0 + r][tid + 256]);
            float* d0 = &inpT[(9 + tid) * 20];
            float* d1 = &inpT[(9 + tid + 256) * 20];
            #pragma unroll
            for (int q = 0; q < 8; ++q) {
                *(float2*)(d0 + 2 * q) = make_float2(v0[2*q], v0[2*q+1]);
                *(float2*)(d1 + 2 * q) = make_float2(v1[2*q], v1[2*q+1]);
            }
        }
        __syncthreads();

        // ---- Phase C: mainloop. warp kp: k in [kp*68, kp*68+68), all 16 rows,
        //      cols (2*lane, 2*lane+1). acc0 = col even, acc1 = col odd; pairs of rows.
        unsigned long long acc0[8], acc1[8];
        #pragma unroll
        for (int i = 0; i < 8; ++i) { acc0[i] = 0ull; acc1[i] = 0ull; }
        {
            const float* Ip = inpT + warp * 68 * 20;
            const float* Wp = Wsm + warp * 68 * 64 + 2 * lane;
            #pragma unroll 4
            for (int kk = 0; kk < 68; ++kk) {
                unsigned long long pr_[8];
                #pragma unroll
                for (int j = 0; j < 4; ++j) {
                    ulonglong2 q = *(const ulonglong2*)(Ip + kk * 20 + 4 * j);
                    pr_[2 * j] = q.x; pr_[2 * j + 1] = q.y;
                }
                float2 wv = *(const float2*)(Wp + kk * 64);
                unsigned long long w00, w11;
                asm("mov.b64 %0, {%1, %1};" : "=l"(w00) : "f"(wv.x));
                asm("mov.b64 %0, {%1, %1};" : "=l"(w11) : "f"(wv.y));
                #pragma unroll
                for (int p = 0; p < 8; ++p) {
                    asm("fma.rn.f32x2 %0, %1, %2, %0;" : "+l"(acc0[p]) : "l"(pr_[p]), "l"(w00));
                    asm("fma.rn.f32x2 %0, %1, %2, %0;" : "+l"(acc1[p]) : "l"(pr_[p]), "l"(w11));
                }
            }
        }

        // ---- Phase D: spill k-partials, reduce, tanh, emit hx + readout partial ----
        #pragma unroll
        for (int p = 0; p < 8; ++p) {
            float2 a0 = *(float2*)&acc0[p];   // (row 2p, row 2p+1) col even
            float2 a1 = *(float2*)&acc1[p];   // col odd
            *(float2*)&red[(warp * 16 + 2 * p)     * 68 + 2 * lane] = make_float2(a0.x, a1.x);
            *(float2*)&red[(warp * 16 + 2 * p + 1) * 68 + 2 * lane] = make_float2(a0.y, a1.y);
        }
        __syncthreads();
        {
            int r = tid >> 4, c4 = (tid & 15) * 4;
            float4 v = make_float4(0.f, 0.f, 0.f, 0.f);
            #pragma unroll
            for (int w = 0; w < 8; ++w) {
                float4 p = *(const float4*)&red[(w * 16 + r) * 68 + c4];
                v.x += p.x; v.y += p.y; v.z += p.z; v.w += p.w;
            }
            v.x = tanh_ex(v.x + b1s[c4 + 0]);
            v.y = tanh_ex(v.y + b1s[c4 + 1]);
            v.z = tanh_ex(v.z + b1s[c4 + 2]);
            v.w = tanh_ex(v.w + b1s[c4 + 3]);
            *(float4*)&g_hx[pw][row0 + r][cg * 64 + c4] = v;
            float p = v.x * w2s[c4] + v.y * w2s[c4 + 1] + v.z * w2s[c4 + 2] + v.w * w2s[c4 + 3];
            #pragma unroll
            for (int off = 8; off > 0; off >>= 1)
                p += __shfl_xor_sync(0xffffffffu, p, off);
            if ((tid & 15) == 0) g_part[pw][rg][cg][r] = p;
        }

        // ---- Phase E: split cluster barrier; x staging hides in the gap ----
        asm volatile("barrier.cluster.arrive.aligned;" ::: "memory");
        if (t < 1023) {
            if (tid < 128) {
                inpT[xc * 20 + xr] = xpre;                           // stage x_{t+1}
                if (t < 1022) xpre = x[(row0 + xr) * 8192 + (t + 2) * 8 + xc];
            }
            // x0 for next step's Phase A = x_{t+1}[0]
            if (tid < 16) x0pre = x[(row0 + tid) * 8192 + (t + 1) * 8];
        }
        asm volatile("barrier.cluster.wait.aligned;" ::: "memory");
    }

    // epilogue: final output value out_{L-1}
    if (cg == 0 && tid < 16) {
        float o = b2v;
        #pragma unroll
        for (int g = 0; g < 8; ++g) o += __ldcg(&g_part[1][rg][g][tid]);
        outp[(row0 + tid) * 1024 + 1023] = o;
    }
}

extern "C" void kernel_launch(void* const* d_in, const int* in_sizes, int n_in,
                              void* d_out, int out_size) {
    const float* x  = (const float*)d_in[0];
    const float* W1 = (const float*)d_in[1];
    const float* b1 = (const float*)d_in[2];
    const float* W2 = (const float*)d_in[3];
    const float* b2 = (const float*)d_in[4];
    float* out = (float*)d_out;

    cudaFuncSetAttribute(resRNN_kernel, cudaFuncAttributeMaxDynamicSharedMemorySize, SMEM_BYTES);

    dim3 grid(8, 16, 1);   // cluster_dims (8,1,1): one cluster per rowgroup
    dim3 block(TPB, 1, 1);
    resRNN_kernel<<<grid, block, SMEM_BYTES>>>(x, W1, b1, W2, b2, out);
}